// round 10
// baseline (speedup 1.0000x reference)
#include <cuda_runtime.h>
#include <cuda_fp16.h>
#include <math.h>

#define U_N 100000
#define I_N 50000
#define E_N 2000000
#define D_N 128
#define B_N 4096

#define FP8_SCALE 256.0f
#define FP8_INV   (1.0f / 256.0f)

#define CHUNK 1024
#define NCH_U ((U_N + CHUNK - 1) / CHUNK)   // 98
#define NCH_I ((I_N + CHUNK - 1) / CHUNK)   // 49
#define NBLK  (NCH_U + NCH_I)               // 147 (<= 148 SMs: co-resident)
#define PREP_T 256
#define PREP_STRIDE (NBLK * PREP_T)

// ---------------- device scratch (static, allocation-free) ----------------
__device__ unsigned g_f8_u[2][(size_t)U_N * 32];  // fp8 rows ping-pong (12.8 MB each)
__device__ unsigned g_f8_i[2][(size_t)I_N * 32];  // (6.4 MB each)
__device__ int   g_deg_u[U_N];
__device__ int   g_deg_i[I_N];
__device__ int   g_row_u[U_N + 1];
__device__ int   g_row_i[I_N + 1];
__device__ int   g_cur_u[U_N];
__device__ int   g_cur_i[I_N];
__device__ int   g_chunk_u[NCH_U];
__device__ int   g_chunk_i[NCH_I];
__device__ int2  g_adj_u[E_N];   // {item byte-offset (<<7), norm as duplicated half2}
__device__ int2  g_adj_i[E_N];   // {user byte-offset (<<7), norm as duplicated half2}
__device__ float g_acc_u[(size_t)B_N * D_N];
__device__ float g_acc_i[(size_t)B_N * D_N];
__device__ unsigned g_cnt;       // accumulating grid-barrier counter (zeroed in final_kernel)

// ---------------- fp8 helpers (fast packed class) ----------------
__device__ __forceinline__ __half2 e4m3x2_to_h2(unsigned short s) {
    unsigned r;
    asm("cvt.rn.f16x2.e4m3x2 %0, %1;" : "=r"(r) : "h"(s));
    return *reinterpret_cast<__half2*>(&r);
}
__device__ __forceinline__ unsigned short h2_to_e4m3x2(__half2 h) {
    unsigned short s;
    unsigned hr = *reinterpret_cast<unsigned*>(&h);
    asm("cvt.rn.satfinite.e4m3x2.f16x2 %0, %1;" : "=h"(s) : "r"(hr));
    return s;
}
__device__ __forceinline__ unsigned pack_f8x4(__half2 lo, __half2 hi) {
    return (unsigned)h2_to_e4m3x2(lo) | ((unsigned)h2_to_e4m3x2(hi) << 16);
}
__device__ __forceinline__ unsigned ld_off(const unsigned* base, unsigned byte_off) {
    return *reinterpret_cast<const unsigned*>(
        reinterpret_cast<const char*>(base) + byte_off);
}

// ---------------- accumulating grid barrier (phase = 1,2,...) ----------------
__device__ __forceinline__ void pbar(int phase) {
    __syncthreads();
    __threadfence();
    if (threadIdx.x == 0) {
        atomicAdd(&g_cnt, 1u);
        while (*((volatile unsigned*)&g_cnt) < (unsigned)(NBLK * phase)) { }
    }
    __syncthreads();
    __threadfence();
}

// ================= persistent prep kernel: everything before the gathers =================
__global__ void __launch_bounds__(PREP_T) prep_kernel(
        const int4* __restrict__ u_idx4,
        const int4* __restrict__ i_idx4,
        const float4* __restrict__ user_feat,
        const float4* __restrict__ item_feat,
        const int* __restrict__ ui,
        const int* __restrict__ ii,
        float* __restrict__ loss_out,
        int has_loss) {
    int tid0 = blockIdx.x * PREP_T + threadIdx.x;

    // ---- P0: zero degrees + loss ----
    for (int t = tid0; t < U_N; t += PREP_STRIDE) {
        g_deg_u[t] = 0;
        if (t < I_N) g_deg_i[t] = 0;
    }
    if (tid0 == 0 && has_loss) *loss_out = 0.0f;
    pbar(1);

    // ---- P1: degrees + fp8 convert + acc_init (independent, share the phase) ----
    const int NQ = E_N / 4;
    for (int t = tid0; t < NQ; t += PREP_STRIDE) {
        int4 u = u_idx4[t];
        int4 i = i_idx4[t];
        atomicAdd(&g_deg_u[u.x], 1); atomicAdd(&g_deg_u[u.y], 1);
        atomicAdd(&g_deg_u[u.z], 1); atomicAdd(&g_deg_u[u.w], 1);
        atomicAdd(&g_deg_i[i.x], 1); atomicAdd(&g_deg_i[i.y], 1);
        atomicAdd(&g_deg_i[i.z], 1); atomicAdd(&g_deg_i[i.w], 1);
    }
    const int nu = U_N * 32;
    const int ni = I_N * 32;
    for (int t = tid0; t < nu + ni; t += PREP_STRIDE) {
        float4 v; unsigned* dst; int o;
        if (t < nu) { v = user_feat[t]; dst = g_f8_u[0]; o = t; }
        else        { o = t - nu; v = item_feat[o]; dst = g_f8_i[0]; }
        __half2 lo = __floats2half2_rn(v.x * FP8_SCALE, v.y * FP8_SCALE);
        __half2 hi = __floats2half2_rn(v.z * FP8_SCALE, v.w * FP8_SCALE);
        dst[o] = pack_f8x4(lo, hi);
    }
    for (int t = tid0; t < B_N * 32; t += PREP_STRIDE) {
        int b = t >> 5;
        int d = t & 31;
        ((float4*)g_acc_u)[t] = user_feat[(size_t)ui[b] * 32 + d];
        ((float4*)g_acc_i)[t] = item_feat[(size_t)ii[b] * 32 + d];
    }
    pbar(2);

    // ---- P2: per-chunk partial sums (block == chunk; NBLK == NCH_U+NCH_I) ----
    {
        bool isU = blockIdx.x < NCH_U;
        const int* deg = isU ? g_deg_u : g_deg_i;
        int* part      = isU ? g_chunk_u : g_chunk_i;
        int  c         = isU ? blockIdx.x : blockIdx.x - NCH_U;
        int  n         = isU ? U_N : I_N;
        int base = c * CHUNK + threadIdx.x * 4;
        int s = 0;
        #pragma unroll
        for (int j = 0; j < 4; j++) {
            int idx = base + j;
            if (idx < n) s += __ldcg(&deg[idx]);
        }
        #pragma unroll
        for (int o = 16; o > 0; o >>= 1) s += __shfl_down_sync(0xFFFFFFFFu, s, o);
        __shared__ int ws[8];
        if ((threadIdx.x & 31) == 0) ws[threadIdx.x >> 5] = s;
        __syncthreads();
        if (threadIdx.x < 8) {
            int v = ws[threadIdx.x];
            #pragma unroll
            for (int o = 4; o > 0; o >>= 1) v += __shfl_down_sync(0xFFu, v, o);
            if (threadIdx.x == 0) part[c] = v;
        }
    }
    pbar(3);

    // ---- P3: block 0 scans both partial arrays ----
    if (blockIdx.x == 0) {
        __shared__ int buf[256];
        int t = threadIdx.x;
        int v = (t < NCH_U) ? __ldcg(&g_chunk_u[t]) : 0;
        buf[t] = v; __syncthreads();
        #pragma unroll
        for (int o = 1; o < 256; o <<= 1) {
            int x = (t >= o) ? buf[t - o] : 0;
            __syncthreads(); buf[t] += x; __syncthreads();
        }
        if (t < NCH_U) g_chunk_u[t] = buf[t] - v;
        __syncthreads();
        int v2 = (t < NCH_I) ? __ldcg(&g_chunk_i[t]) : 0;
        buf[t] = v2; __syncthreads();
        #pragma unroll
        for (int o = 1; o < 256; o <<= 1) {
            int x = (t >= o) ? buf[t - o] : 0;
            __syncthreads(); buf[t] += x; __syncthreads();
        }
        if (t < NCH_I) g_chunk_i[t] = buf[t] - v2;
        if (t == 0) { g_row_u[U_N] = E_N; g_row_i[I_N] = E_N; }
    }
    pbar(4);

    // ---- P4: per-chunk local scan + chunk base; init cursors ----
    {
        bool isU = blockIdx.x < NCH_U;
        const int* deg = isU ? g_deg_u : g_deg_i;
        int* row       = isU ? g_row_u : g_row_i;
        int* cur       = isU ? g_cur_u : g_cur_i;
        int  c         = isU ? blockIdx.x : blockIdx.x - NCH_U;
        int  n         = isU ? U_N : I_N;
        int  cbase     = isU ? __ldcg(&g_chunk_u[c]) : __ldcg(&g_chunk_i[c]);

        int base = c * CHUNK + threadIdx.x * 4;
        int d[4], e[4];
        int s = 0;
        #pragma unroll
        for (int j = 0; j < 4; j++) {
            int idx = base + j;
            d[j] = (idx < n) ? __ldcg(&deg[idx]) : 0;
            e[j] = s;
            s += d[j];
        }
        int lane = threadIdx.x & 31, w = threadIdx.x >> 5;
        int inc = s;
        #pragma unroll
        for (int o = 1; o < 32; o <<= 1) {
            int x = __shfl_up_sync(0xFFFFFFFFu, inc, o);
            if (lane >= o) inc += x;
        }
        __shared__ int ws2[8];
        if (lane == 31) ws2[w] = inc;
        __syncthreads();
        if (threadIdx.x < 8) {
            int v = ws2[threadIdx.x];
            #pragma unroll
            for (int o = 1; o < 8; o <<= 1) {
                int x = __shfl_up_sync(0xFFu, v, o);
                if ((int)threadIdx.x >= o) v += x;
            }
            ws2[threadIdx.x] = v;
        }
        __syncthreads();
        int excl = inc - s + (w > 0 ? ws2[w - 1] : 0) + cbase;
        #pragma unroll
        for (int j = 0; j < 4; j++) {
            int idx = base + j;
            if (idx < n) { int r = excl + e[j]; row[idx] = r; cur[idx] = r; }
        }
    }
    pbar(5);

    // ---- P5: CSR fill (columns pre-shifted to byte offsets) ----
    for (int t = tid0; t < NQ; t += PREP_STRIDE) {
        int4 u4 = u_idx4[t];
        int4 i4 = i_idx4[t];
        #pragma unroll
        for (int j = 0; j < 4; j++) {
            int u = (j == 0) ? u4.x : (j == 1) ? u4.y : (j == 2) ? u4.z : u4.w;
            int i = (j == 0) ? i4.x : (j == 1) ? i4.y : (j == 2) ? i4.z : i4.w;
            float nf = rsqrtf((float)g_deg_u[u] * (float)g_deg_i[i]);
            __half2 h2 = __half2half2(__float2half_rn(nf));
            int nb = *reinterpret_cast<int*>(&h2);
            int pu = atomicAdd(&g_cur_u[u], 1);
            g_adj_u[pu] = make_int2(i << 7, nb);
            int pi = atomicAdd(&g_cur_i[i], 1);
            g_adj_i[pi] = make_int2(u << 7, nb);
        }
    }
    // no trailing barrier: next kernel is stream-ordered
}

// ---------------- gather: warp per row, lane owns one uint32; fused acc warps ----------------
__global__ void gather_kernel(const unsigned* __restrict__ s8_u,
                              const unsigned* __restrict__ s8_i,
                              unsigned* __restrict__ d8_u,
                              unsigned* __restrict__ d8_i,
                              const int* __restrict__ ui,
                              const int* __restrict__ ii,
                              float acc_coef) {
    int w = (blockIdx.x * blockDim.x + threadIdx.x) >> 5;
    int lane = threadIdx.x & 31;

    if (w >= U_N + I_N) {
        int b = w - (U_N + I_N);
        if (b >= B_N || acc_coef == 0.0f) return;
        float c = acc_coef * FP8_INV;
        int t = b * 32 + lane;
        unsigned q = s8_u[(size_t)ui[b] * 32 + lane];
        float2 p = __half22float2(e4m3x2_to_h2((unsigned short)(q & 0xFFFFu)));
        float2 r = __half22float2(e4m3x2_to_h2((unsigned short)(q >> 16)));
        float4 a = ((float4*)g_acc_u)[t];
        a.x += c * p.x; a.y += c * p.y; a.z += c * r.x; a.w += c * r.y;
        ((float4*)g_acc_u)[t] = a;
        unsigned q2 = s8_i[(size_t)ii[b] * 32 + lane];
        p = __half22float2(e4m3x2_to_h2((unsigned short)(q2 & 0xFFFFu)));
        r = __half22float2(e4m3x2_to_h2((unsigned short)(q2 >> 16)));
        float4 ai = ((float4*)g_acc_i)[t];
        ai.x += c * p.x; ai.y += c * p.y; ai.z += c * r.x; ai.w += c * r.y;
        ((float4*)g_acc_i)[t] = ai;
        return;
    }

    const int* rp; const int2* adj;
    const unsigned* src; const unsigned* self; unsigned* dst; int d;
    if (w < U_N) {
        d = w; rp = g_row_u; adj = g_adj_u;
        src = s8_i; self = s8_u; dst = d8_u;
    } else {
        d = w - U_N; rp = g_row_i; adj = g_adj_i;
        src = s8_u; self = s8_i; dst = d8_i;
    }

    int start = rp[d];
    int end   = rp[d + 1];
    unsigned lane_off = (unsigned)lane << 2;

    unsigned sv = self[(size_t)d * 32 + lane];
    __half2 a01 = e4m3x2_to_h2((unsigned short)(sv & 0xFFFFu));
    __half2 a23 = e4m3x2_to_h2((unsigned short)(sv >> 16));

    int k = start;
    if ((k & 1) && k < end) {   // peel to even k for aligned int4 adjacency loads
        int2 e0 = adj[k];
        unsigned v0 = ld_off(src, (unsigned)e0.x | lane_off);
        __half2 n0 = *reinterpret_cast<__half2*>(&e0.y);
        a01 = __hfma2(e4m3x2_to_h2((unsigned short)(v0 & 0xFFFFu)), n0, a01);
        a23 = __hfma2(e4m3x2_to_h2((unsigned short)(v0 >> 16)),     n0, a23);
        k++;
    }
    for (; k + 4 <= end; k += 4) {
        const int4* p4 = reinterpret_cast<const int4*>(adj + k);
        int4 A = p4[0];   // edges k, k+1 (x,z pre-shifted byte offsets)
        int4 B = p4[1];   // edges k+2, k+3
        unsigned v0 = ld_off(src, (unsigned)A.x | lane_off);
        unsigned v1 = ld_off(src, (unsigned)A.z | lane_off);
        unsigned v2 = ld_off(src, (unsigned)B.x | lane_off);
        unsigned v3 = ld_off(src, (unsigned)B.z | lane_off);
        __half2 n0 = *reinterpret_cast<__half2*>(&A.y);
        __half2 n1 = *reinterpret_cast<__half2*>(&A.w);
        __half2 n2 = *reinterpret_cast<__half2*>(&B.y);
        __half2 n3 = *reinterpret_cast<__half2*>(&B.w);
        a01 = __hfma2(e4m3x2_to_h2((unsigned short)(v0 & 0xFFFFu)), n0, a01);
        a23 = __hfma2(e4m3x2_to_h2((unsigned short)(v0 >> 16)),     n0, a23);
        a01 = __hfma2(e4m3x2_to_h2((unsigned short)(v1 & 0xFFFFu)), n1, a01);
        a23 = __hfma2(e4m3x2_to_h2((unsigned short)(v1 >> 16)),     n1, a23);
        a01 = __hfma2(e4m3x2_to_h2((unsigned short)(v2 & 0xFFFFu)), n2, a01);
        a23 = __hfma2(e4m3x2_to_h2((unsigned short)(v2 >> 16)),     n2, a23);
        a01 = __hfma2(e4m3x2_to_h2((unsigned short)(v3 & 0xFFFFu)), n3, a01);
        a23 = __hfma2(e4m3x2_to_h2((unsigned short)(v3 >> 16)),     n3, a23);
    }
    for (; k < end; k++) {
        int2 e0 = adj[k];
        unsigned v0 = ld_off(src, (unsigned)e0.x | lane_off);
        __half2 n0 = *reinterpret_cast<__half2*>(&e0.y);
        a01 = __hfma2(e4m3x2_to_h2((unsigned short)(v0 & 0xFFFFu)), n0, a01);
        a23 = __hfma2(e4m3x2_to_h2((unsigned short)(v0 >> 16)),     n0, a23);
    }

    dst[(size_t)d * 32 + lane] = pack_f8x4(a01, a23);
}

// ---------------- fused final: last-layer acc + dot + sigmoid + BCE + counter reset ----------------
__global__ void final_kernel(const unsigned* __restrict__ h3_u,
                             const unsigned* __restrict__ h3_i,
                             const int* __restrict__ ui,
                             const int* __restrict__ ii,
                             const float* __restrict__ labels,
                             float* __restrict__ pred_out,
                             float* __restrict__ loss_out,
                             int has_loss) {
    int b = (blockIdx.x * blockDim.x + threadIdx.x) >> 5;
    int lane = threadIdx.x & 31;
    if (b >= B_N) return;
    if (b == 0 && lane == 0) g_cnt = 0;   // reset grid-barrier counter for next launch

    const float c = 0.25f * FP8_INV;   // layer-3 coefficient
    int t = b * 32 + lane;

    float4 a = ((const float4*)g_acc_u)[t];
    unsigned q = h3_u[(size_t)ui[b] * 32 + lane];
    float2 p = __half22float2(e4m3x2_to_h2((unsigned short)(q & 0xFFFFu)));
    float2 r = __half22float2(e4m3x2_to_h2((unsigned short)(q >> 16)));
    a.x += c * p.x; a.y += c * p.y; a.z += c * r.x; a.w += c * r.y;

    float4 ai = ((const float4*)g_acc_i)[t];
    unsigned q2 = h3_i[(size_t)ii[b] * 32 + lane];
    p = __half22float2(e4m3x2_to_h2((unsigned short)(q2 & 0xFFFFu)));
    r = __half22float2(e4m3x2_to_h2((unsigned short)(q2 >> 16)));
    ai.x += c * p.x; ai.y += c * p.y; ai.z += c * r.x; ai.w += c * r.y;

    float s = a.x * ai.x + a.y * ai.y + a.z * ai.z + a.w * ai.w;
    #pragma unroll
    for (int o = 16; o > 0; o >>= 1)
        s += __shfl_down_sync(0xFFFFFFFFu, s, o);

    if (lane == 0) {
        float z = 1.0f / (1.0f + expf(-s));
        pred_out[b] = z;
        if (has_loss) {
            float lbl = labels[b];
            float term = fmaxf(z, 0.0f) - z * lbl + log1pf(expf(-fabsf(z)));
            atomicAdd(loss_out, term * (1.0f / (float)B_N));
        }
    }
}

// ---------------- host launch ----------------
extern "C" void kernel_launch(void* const* d_in, const int* in_sizes, int n_in,
                              void* d_out, int out_size) {
    const float* user_feat = (const float*)d_in[0];
    const float* item_feat = (const float*)d_in[1];
    const int*   u_idx     = (const int*)d_in[2];
    const int*   i_idx     = (const int*)d_in[3];
    const int*   ui        = (const int*)d_in[4];
    const int*   ii        = (const int*)d_in[5];
    const float* labels    = (const float*)d_in[6];

    float* out = (float*)d_out;
    int has_loss = (out_size > B_N) ? 1 : 0;
    float* pred_out = out + (out_size - B_N);
    float* loss_out = out;

    unsigned *hu_base, *hi_base;
    cudaGetSymbolAddress((void**)&hu_base, g_f8_u);
    cudaGetSymbolAddress((void**)&hi_base, g_f8_i);
    unsigned* hu[2] = { hu_base, hu_base + (size_t)U_N * 32 };
    unsigned* hi[2] = { hi_base, hi_base + (size_t)I_N * 32 };

    const int T = 256;
    const int gather_blocks = ((U_N + I_N + B_N) * 32 + T - 1) / T;

    // 1) persistent prep: zero + degrees + convert + acc_init + scan + fill
    prep_kernel<<<NBLK, PREP_T>>>((const int4*)u_idx, (const int4*)i_idx,
                                  (const float4*)user_feat,
                                  (const float4*)item_feat,
                                  ui, ii, loss_out, has_loss);

    // 2) three propagation layers; each also applies the previous layer's acc
    const float coefs[3] = { 0.5f, 1.0f / 3.0f, 0.25f };
    int cur = 0;
    for (int l = 0; l < 3; l++) {
        int nxt = 1 - cur;
        float prev_coef = (l == 0) ? 0.0f : coefs[l - 1];
        gather_kernel<<<gather_blocks, T>>>(hu[cur], hi[cur],
                                            hu[nxt], hi[nxt],
                                            ui, ii, prev_coef);
        cur = nxt;
    }

    // 3) fused final: layer-3 acc + dot + sigmoid + BCE (+ barrier counter reset)
    final_kernel<<<(B_N * 32 + T - 1) / T, T>>>(hu[cur], hi[cur],
                                                ui, ii, labels,
                                                pred_out, loss_out, has_loss);
}

// round 11
// speedup vs baseline: 1.1504x; 1.1504x over previous
#include <cuda_runtime.h>
#include <cuda_fp16.h>
#include <math.h>

#define U_N 100000
#define I_N 50000
#define E_N 2000000
#define D_N 128
#define B_N 4096

#define FP8_SCALE 256.0f
#define FP8_INV   (1.0f / 256.0f)

#define CHUNK 1024
#define NCH_U ((U_N + CHUNK - 1) / CHUNK)   // 98
#define NCH_I ((I_N + CHUNK - 1) / CHUNK)   // 49

// ---------------- device scratch (static, allocation-free) ----------------
__device__ unsigned g_f8_u[2][(size_t)U_N * 32];  // fp8 rows ping-pong (12.8 MB each)
__device__ unsigned g_f8_i[2][(size_t)I_N * 32];  // (6.4 MB each)
__device__ int   g_deg_u[U_N];
__device__ int   g_deg_i[I_N];
__device__ int   g_row_u[U_N + 1];
__device__ int   g_row_i[I_N + 1];
__device__ int   g_cur_u[U_N];
__device__ int   g_cur_i[I_N];
__device__ int   g_chunk_u[NCH_U];
__device__ int   g_chunk_i[NCH_I];
__device__ int2  g_adj_u[E_N];   // {item byte-offset (<<7), norm as duplicated half2}
__device__ int2  g_adj_i[E_N];   // {user byte-offset (<<7), norm as duplicated half2}
__device__ float g_acc_u[(size_t)B_N * D_N];
__device__ float g_acc_i[(size_t)B_N * D_N];

// ---------------- fp8 helpers (fast packed class) ----------------
__device__ __forceinline__ __half2 e4m3x2_to_h2(unsigned short s) {
    unsigned r;
    asm("cvt.rn.f16x2.e4m3x2 %0, %1;" : "=r"(r) : "h"(s));
    return *reinterpret_cast<__half2*>(&r);
}
__device__ __forceinline__ unsigned short h2_to_e4m3x2(__half2 h) {
    unsigned short s;
    unsigned hr = *reinterpret_cast<unsigned*>(&h);
    asm("cvt.rn.satfinite.e4m3x2.f16x2 %0, %1;" : "=h"(s) : "r"(hr));
    return s;
}
__device__ __forceinline__ unsigned pack_f8x4(__half2 lo, __half2 hi) {
    return (unsigned)h2_to_e4m3x2(lo) | ((unsigned)h2_to_e4m3x2(hi) << 16);
}
__device__ __forceinline__ unsigned ld_off(const unsigned* base, unsigned byte_off) {
    return *reinterpret_cast<const unsigned*>(
        reinterpret_cast<const char*>(base) + byte_off);
}

// ---------------- fused init: zero degrees + acc_init + loss zero ----------------
__global__ void init_kernel(const float4* __restrict__ user_feat,
                            const float4* __restrict__ item_feat,
                            const int* __restrict__ ui,
                            const int* __restrict__ ii,
                            float* __restrict__ loss_out,
                            int has_loss) {
    const int ZBLK = (U_N + 255) / 256;
    if (blockIdx.x < ZBLK) {
        int t = blockIdx.x * 256 + threadIdx.x;
        if (t < U_N) g_deg_u[t] = 0;
        if (t < I_N) g_deg_i[t] = 0;
        if (t == 0 && has_loss) *loss_out = 0.0f;
        return;
    }
    int t = (blockIdx.x - ZBLK) * 256 + threadIdx.x;  // over B*32
    if (t >= B_N * 32) return;
    int b = t >> 5;
    int d = t & 31;
    ((float4*)g_acc_u)[t] = user_feat[(size_t)ui[b] * 32 + d];
    ((float4*)g_acc_i)[t] = item_feat[(size_t)ii[b] * 32 + d];
}

// ---------------- degree (4 edges/thread, int4 index loads) ----------------
__global__ void degree_kernel(const int4* __restrict__ u_idx4,
                              const int4* __restrict__ i_idx4) {
    int t = blockIdx.x * blockDim.x + threadIdx.x;
    if (t >= E_N / 4) return;
    int4 u = u_idx4[t];
    int4 i = i_idx4[t];
    atomicAdd(&g_deg_u[u.x], 1); atomicAdd(&g_deg_u[u.y], 1);
    atomicAdd(&g_deg_u[u.z], 1); atomicAdd(&g_deg_u[u.w], 1);
    atomicAdd(&g_deg_i[i.x], 1); atomicAdd(&g_deg_i[i.y], 1);
    atomicAdd(&g_deg_i[i.z], 1); atomicAdd(&g_deg_i[i.w], 1);
}

// ---------------- scan phase A: per-chunk partial sums ----------------
__global__ void scan_partial_kernel() {
    bool isU = blockIdx.x < NCH_U;
    const int* deg = isU ? g_deg_u : g_deg_i;
    int* part      = isU ? g_chunk_u : g_chunk_i;
    int  c         = isU ? blockIdx.x : blockIdx.x - NCH_U;
    int  n         = isU ? U_N : I_N;

    int base = c * CHUNK + threadIdx.x * 4;
    int s = 0;
    #pragma unroll
    for (int j = 0; j < 4; j++) {
        int idx = base + j;
        if (idx < n) s += deg[idx];
    }
    #pragma unroll
    for (int o = 16; o > 0; o >>= 1) s += __shfl_down_sync(0xFFFFFFFFu, s, o);
    __shared__ int ws[8];
    if ((threadIdx.x & 31) == 0) ws[threadIdx.x >> 5] = s;
    __syncthreads();
    if (threadIdx.x < 8) {
        int v = ws[threadIdx.x];
        #pragma unroll
        for (int o = 4; o > 0; o >>= 1) v += __shfl_down_sync(0xFFu, v, o);
        if (threadIdx.x == 0) part[c] = v;
    }
}

// ---------------- scan phase B: one block scans both partial arrays ----------------
__global__ void scan_chunkoff_kernel() {
    __shared__ int buf[128];
    int t = threadIdx.x;

    int v = (t < NCH_U) ? g_chunk_u[t] : 0;
    buf[t] = v; __syncthreads();
    #pragma unroll
    for (int o = 1; o < 128; o <<= 1) {
        int x = (t >= o) ? buf[t - o] : 0;
        __syncthreads(); buf[t] += x; __syncthreads();
    }
    if (t < NCH_U) g_chunk_u[t] = buf[t] - v;
    __syncthreads();

    int v2 = (t < NCH_I) ? g_chunk_i[t] : 0;
    buf[t] = v2; __syncthreads();
    #pragma unroll
    for (int o = 1; o < 128; o <<= 1) {
        int x = (t >= o) ? buf[t - o] : 0;
        __syncthreads(); buf[t] += x; __syncthreads();
    }
    if (t < NCH_I) g_chunk_i[t] = buf[t] - v2;
    if (t == 0) { g_row_u[U_N] = E_N; g_row_i[I_N] = E_N; }
}

// ---------------- scan phase C: local scan + base; init cursors ----------------
__global__ void scan_final_kernel() {
    bool isU = blockIdx.x < NCH_U;
    const int* deg = isU ? g_deg_u : g_deg_i;
    int* row       = isU ? g_row_u : g_row_i;
    int* cur       = isU ? g_cur_u : g_cur_i;
    int  c         = isU ? blockIdx.x : blockIdx.x - NCH_U;
    int  n         = isU ? U_N : I_N;
    int  cbase     = isU ? g_chunk_u[c] : g_chunk_i[c];

    int base = c * CHUNK + threadIdx.x * 4;
    int d[4], e[4];
    int s = 0;
    #pragma unroll
    for (int j = 0; j < 4; j++) {
        int idx = base + j;
        d[j] = (idx < n) ? deg[idx] : 0;
        e[j] = s;
        s += d[j];
    }
    int lane = threadIdx.x & 31, w = threadIdx.x >> 5;
    int inc = s;
    #pragma unroll
    for (int o = 1; o < 32; o <<= 1) {
        int x = __shfl_up_sync(0xFFFFFFFFu, inc, o);
        if (lane >= o) inc += x;
    }
    __shared__ int ws[8];
    if (lane == 31) ws[w] = inc;
    __syncthreads();
    if (threadIdx.x < 8) {
        int v = ws[threadIdx.x];
        #pragma unroll
        for (int o = 1; o < 8; o <<= 1) {
            int x = __shfl_up_sync(0xFFu, v, o);
            if ((int)threadIdx.x >= o) v += x;
        }
        ws[threadIdx.x] = v;
    }
    __syncthreads();
    int excl = inc - s + (w > 0 ? ws[w - 1] : 0) + cbase;
    #pragma unroll
    for (int j = 0; j < 4; j++) {
        int idx = base + j;
        if (idx < n) { int r = excl + e[j]; row[idx] = r; cur[idx] = r; }
    }
}

// ---------------- fused fill (CSR adjacency, pre-shifted cols) + fp8 convert ----------------
#define FILL_BLOCKS_EXACT ((E_N / 4 + 255) / 256)         // 1954
#define CONV_BLOCKS (((U_N + I_N) * 32 + 255) / 256)      // 18750

__global__ void fillconv_kernel(const int4* __restrict__ u_idx4,
                                const int4* __restrict__ i_idx4,
                                const float4* __restrict__ user_feat,
                                const float4* __restrict__ item_feat) {
    if (blockIdx.x < FILL_BLOCKS_EXACT) {
        int t = blockIdx.x * 256 + threadIdx.x;
        if (t >= E_N / 4) return;
        int4 u4 = u_idx4[t];
        int4 i4 = i_idx4[t];
        #pragma unroll
        for (int j = 0; j < 4; j++) {
            int u = (j == 0) ? u4.x : (j == 1) ? u4.y : (j == 2) ? u4.z : u4.w;
            int i = (j == 0) ? i4.x : (j == 1) ? i4.y : (j == 2) ? i4.z : i4.w;
            float nf = rsqrtf((float)g_deg_u[u] * (float)g_deg_i[i]);
            __half2 h2 = __half2half2(__float2half_rn(nf));
            int nb = *reinterpret_cast<int*>(&h2);
            int pu = atomicAdd(&g_cur_u[u], 1);
            g_adj_u[pu] = make_int2(i << 7, nb);   // byte offset of row
            int pi = atomicAdd(&g_cur_i[i], 1);
            g_adj_i[pi] = make_int2(u << 7, nb);
        }
        return;
    }
    int t = (blockIdx.x - FILL_BLOCKS_EXACT) * 256 + threadIdx.x;
    const int nu = U_N * 32;
    const int ni = I_N * 32;
    float4 v; unsigned* dst; int o;
    if (t < nu)           { v = user_feat[t]; dst = g_f8_u[0]; o = t; }
    else if (t < nu + ni) { o = t - nu; v = item_feat[o]; dst = g_f8_i[0]; }
    else return;
    __half2 lo = __floats2half2_rn(v.x * FP8_SCALE, v.y * FP8_SCALE);
    __half2 hi = __floats2half2_rn(v.z * FP8_SCALE, v.w * FP8_SCALE);
    dst[o] = pack_f8x4(lo, hi);
}

// ---------------- gather: warp per row, lane owns one uint32; fused acc warps ----------------
__global__ void gather_kernel(const unsigned* __restrict__ s8_u,
                              const unsigned* __restrict__ s8_i,
                              unsigned* __restrict__ d8_u,
                              unsigned* __restrict__ d8_i,
                              const int* __restrict__ ui,
                              const int* __restrict__ ii,
                              float acc_coef) {
    int w = (blockIdx.x * blockDim.x + threadIdx.x) >> 5;
    int lane = threadIdx.x & 31;

    if (w >= U_N + I_N) {
        int b = w - (U_N + I_N);
        if (b >= B_N || acc_coef == 0.0f) return;
        float c = acc_coef * FP8_INV;
        int t = b * 32 + lane;
        unsigned q = s8_u[(size_t)ui[b] * 32 + lane];
        float2 p = __half22float2(e4m3x2_to_h2((unsigned short)(q & 0xFFFFu)));
        float2 r = __half22float2(e4m3x2_to_h2((unsigned short)(q >> 16)));
        float4 a = ((float4*)g_acc_u)[t];
        a.x += c * p.x; a.y += c * p.y; a.z += c * r.x; a.w += c * r.y;
        ((float4*)g_acc_u)[t] = a;
        unsigned q2 = s8_i[(size_t)ii[b] * 32 + lane];
        p = __half22float2(e4m3x2_to_h2((unsigned short)(q2 & 0xFFFFu)));
        r = __half22float2(e4m3x2_to_h2((unsigned short)(q2 >> 16)));
        float4 ai = ((float4*)g_acc_i)[t];
        ai.x += c * p.x; ai.y += c * p.y; ai.z += c * r.x; ai.w += c * r.y;
        ((float4*)g_acc_i)[t] = ai;
        return;
    }

    const int* rp; const int2* adj;
    const unsigned* src; const unsigned* self; unsigned* dst; int d;
    if (w < U_N) {
        d = w; rp = g_row_u; adj = g_adj_u;
        src = s8_i; self = s8_u; dst = d8_u;
    } else {
        d = w - U_N; rp = g_row_i; adj = g_adj_i;
        src = s8_u; self = s8_i; dst = d8_i;
    }

    int start = rp[d];
    int end   = rp[d + 1];
    unsigned lane_off = (unsigned)lane << 2;

    unsigned sv = self[(size_t)d * 32 + lane];
    __half2 a01 = e4m3x2_to_h2((unsigned short)(sv & 0xFFFFu));
    __half2 a23 = e4m3x2_to_h2((unsigned short)(sv >> 16));

    int k = start;
    if ((k & 1) && k < end) {   // peel to even k for aligned int4 adjacency loads
        int2 e0 = adj[k];
        unsigned v0 = ld_off(src, (unsigned)e0.x | lane_off);
        __half2 n0 = *reinterpret_cast<__half2*>(&e0.y);
        a01 = __hfma2(e4m3x2_to_h2((unsigned short)(v0 & 0xFFFFu)), n0, a01);
        a23 = __hfma2(e4m3x2_to_h2((unsigned short)(v0 >> 16)),     n0, a23);
        k++;
    }
    for (; k + 4 <= end; k += 4) {
        const int4* p4 = reinterpret_cast<const int4*>(adj + k);
        int4 A = p4[0];   // edges k, k+1 (x,z pre-shifted byte offsets)
        int4 B = p4[1];   // edges k+2, k+3
        unsigned v0 = ld_off(src, (unsigned)A.x | lane_off);
        unsigned v1 = ld_off(src, (unsigned)A.z | lane_off);
        unsigned v2 = ld_off(src, (unsigned)B.x | lane_off);
        unsigned v3 = ld_off(src, (unsigned)B.z | lane_off);
        __half2 n0 = *reinterpret_cast<__half2*>(&A.y);
        __half2 n1 = *reinterpret_cast<__half2*>(&A.w);
        __half2 n2 = *reinterpret_cast<__half2*>(&B.y);
        __half2 n3 = *reinterpret_cast<__half2*>(&B.w);
        a01 = __hfma2(e4m3x2_to_h2((unsigned short)(v0 & 0xFFFFu)), n0, a01);
        a23 = __hfma2(e4m3x2_to_h2((unsigned short)(v0 >> 16)),     n0, a23);
        a01 = __hfma2(e4m3x2_to_h2((unsigned short)(v1 & 0xFFFFu)), n1, a01);
        a23 = __hfma2(e4m3x2_to_h2((unsigned short)(v1 >> 16)),     n1, a23);
        a01 = __hfma2(e4m3x2_to_h2((unsigned short)(v2 & 0xFFFFu)), n2, a01);
        a23 = __hfma2(e4m3x2_to_h2((unsigned short)(v2 >> 16)),     n2, a23);
        a01 = __hfma2(e4m3x2_to_h2((unsigned short)(v3 & 0xFFFFu)), n3, a01);
        a23 = __hfma2(e4m3x2_to_h2((unsigned short)(v3 >> 16)),     n3, a23);
    }
    for (; k < end; k++) {
        int2 e0 = adj[k];
        unsigned v0 = ld_off(src, (unsigned)e0.x | lane_off);
        __half2 n0 = *reinterpret_cast<__half2*>(&e0.y);
        a01 = __hfma2(e4m3x2_to_h2((unsigned short)(v0 & 0xFFFFu)), n0, a01);
        a23 = __hfma2(e4m3x2_to_h2((unsigned short)(v0 >> 16)),     n0, a23);
    }

    dst[(size_t)d * 32 + lane] = pack_f8x4(a01, a23);
}

// ---------------- fused final: last-layer acc + dot + sigmoid + BCE ----------------
__global__ void final_kernel(const unsigned* __restrict__ h3_u,
                             const unsigned* __restrict__ h3_i,
                             const int* __restrict__ ui,
                             const int* __restrict__ ii,
                             const float* __restrict__ labels,
                             float* __restrict__ pred_out,
                             float* __restrict__ loss_out,
                             int has_loss) {
    int b = (blockIdx.x * blockDim.x + threadIdx.x) >> 5;
    int lane = threadIdx.x & 31;
    if (b >= B_N) return;

    const float c = 0.25f * FP8_INV;   // layer-3 coefficient
    int t = b * 32 + lane;

    float4 a = ((const float4*)g_acc_u)[t];
    unsigned q = h3_u[(size_t)ui[b] * 32 + lane];
    float2 p = __half22float2(e4m3x2_to_h2((unsigned short)(q & 0xFFFFu)));
    float2 r = __half22float2(e4m3x2_to_h2((unsigned short)(q >> 16)));
    a.x += c * p.x; a.y += c * p.y; a.z += c * r.x; a.w += c * r.y;

    float4 ai = ((const float4*)g_acc_i)[t];
    unsigned q2 = h3_i[(size_t)ii[b] * 32 + lane];
    p = __half22float2(e4m3x2_to_h2((unsigned short)(q2 & 0xFFFFu)));
    r = __half22float2(e4m3x2_to_h2((unsigned short)(q2 >> 16)));
    ai.x += c * p.x; ai.y += c * p.y; ai.z += c * r.x; ai.w += c * r.y;

    float s = a.x * ai.x + a.y * ai.y + a.z * ai.z + a.w * ai.w;
    #pragma unroll
    for (int o = 16; o > 0; o >>= 1)
        s += __shfl_down_sync(0xFFFFFFFFu, s, o);

    if (lane == 0) {
        float z = 1.0f / (1.0f + expf(-s));
        pred_out[b] = z;
        if (has_loss) {
            float lbl = labels[b];
            float term = fmaxf(z, 0.0f) - z * lbl + log1pf(expf(-fabsf(z)));
            atomicAdd(loss_out, term * (1.0f / (float)B_N));
        }
    }
}

// ---------------- host launch ----------------
extern "C" void kernel_launch(void* const* d_in, const int* in_sizes, int n_in,
                              void* d_out, int out_size) {
    const float* user_feat = (const float*)d_in[0];
    const float* item_feat = (const float*)d_in[1];
    const int*   u_idx     = (const int*)d_in[2];
    const int*   i_idx     = (const int*)d_in[3];
    const int*   ui        = (const int*)d_in[4];
    const int*   ii        = (const int*)d_in[5];
    const float* labels    = (const float*)d_in[6];

    float* out = (float*)d_out;
    int has_loss = (out_size > B_N) ? 1 : 0;
    float* pred_out = out + (out_size - B_N);
    float* loss_out = out;

    unsigned *hu_base, *hi_base;
    cudaGetSymbolAddress((void**)&hu_base, g_f8_u);
    cudaGetSymbolAddress((void**)&hi_base, g_f8_i);
    unsigned* hu[2] = { hu_base, hu_base + (size_t)U_N * 32 };
    unsigned* hi[2] = { hi_base, hi_base + (size_t)I_N * 32 };

    const int T = 256;
    const int ZBLK = (U_N + 255) / 256;
    const int init_blocks = ZBLK + (B_N * 32 + 255) / 256;
    const int deg_blocks = (E_N / 4 + T - 1) / T;
    const int fillconv_blocks = FILL_BLOCKS_EXACT + CONV_BLOCKS;
    const int gather_blocks = ((U_N + I_N + B_N) * 32 + T - 1) / T;

    // 1) fused init (zero degrees, acc layer-0 from exact fp32, zero loss)
    init_kernel<<<init_blocks, T>>>((const float4*)user_feat,
                                    (const float4*)item_feat,
                                    ui, ii, loss_out, has_loss);
    // 2) degrees
    degree_kernel<<<deg_blocks, T>>>((const int4*)u_idx, (const int4*)i_idx);
    // 3) row-pointer scan (3 small kernels — measured faster than persistent fusion)
    scan_partial_kernel<<<NCH_U + NCH_I, 256>>>();
    scan_chunkoff_kernel<<<1, 128>>>();
    scan_final_kernel<<<NCH_U + NCH_I, 256>>>();
    // 4) fused CSR fill (pre-shifted byte-offset columns) + fp8 convert
    fillconv_kernel<<<fillconv_blocks, T>>>((const int4*)u_idx, (const int4*)i_idx,
                                            (const float4*)user_feat,
                                            (const float4*)item_feat);

    // 5) three propagation layers; each also applies the previous layer's acc
    const float coefs[3] = { 0.5f, 1.0f / 3.0f, 0.25f };
    int cur = 0;
    for (int l = 0; l < 3; l++) {
        int nxt = 1 - cur;
        float prev_coef = (l == 0) ? 0.0f : coefs[l - 1];
        gather_kernel<<<gather_blocks, T>>>(hu[cur], hi[cur],
                                            hu[nxt], hi[nxt],
                                            ui, ii, prev_coef);
        cur = nxt;
    }

    // 6) fused final: layer-3 acc + dot + sigmoid + BCE
    final_kernel<<<(B_N * 32 + T - 1) / T, T>>>(hu[cur], hi[cur],
                                                ui, ii, labels,
                                                pred_out, loss_out, has_loss);
}

// round 12
// speedup vs baseline: 1.2193x; 1.0599x over previous
#include <cuda_runtime.h>
#include <cuda_fp16.h>
#include <math.h>

#define U_N 100000
#define I_N 50000
#define E_N 2000000
#define D_N 128
#define B_N 4096

#define FP8_SCALE 256.0f
#define FP8_INV   (1.0f / 256.0f)

#define CHUNK 1024
#define NCH_U ((U_N + CHUNK - 1) / CHUNK)   // 98
#define NCH_I ((I_N + CHUNK - 1) / CHUNK)   // 49

// ---------------- device scratch (static, allocation-free) ----------------
__device__ unsigned g_f8_u[2][(size_t)U_N * 32];  // fp8 rows ping-pong (12.8 MB each)
__device__ unsigned g_f8_i[2][(size_t)I_N * 32];  // (6.4 MB each)
__device__ int   g_deg_u[U_N];
__device__ int   g_deg_i[I_N];
__device__ int   g_row_u[U_N + 1];
__device__ int   g_row_i[I_N + 1];
__device__ int   g_cur_u[U_N];
__device__ int   g_cur_i[I_N];
__device__ int   g_chunk_u[NCH_U];
__device__ int   g_chunk_i[NCH_I];
__device__ int2  g_adj_u[E_N];   // {item byte-offset (<<7), norm as duplicated half2}
__device__ int2  g_adj_i[E_N];   // {user byte-offset (<<7), norm as duplicated half2}
__device__ float g_acc_u[(size_t)B_N * D_N];
__device__ float g_acc_i[(size_t)B_N * D_N];

// ---------------- fp8 helpers (fast packed class) ----------------
__device__ __forceinline__ __half2 e4m3x2_to_h2(unsigned short s) {
    unsigned r;
    asm("cvt.rn.f16x2.e4m3x2 %0, %1;" : "=r"(r) : "h"(s));
    return *reinterpret_cast<__half2*>(&r);
}
__device__ __forceinline__ unsigned short h2_to_e4m3x2(__half2 h) {
    unsigned short s;
    unsigned hr = *reinterpret_cast<unsigned*>(&h);
    asm("cvt.rn.satfinite.e4m3x2.f16x2 %0, %1;" : "=h"(s) : "r"(hr));
    return s;
}
__device__ __forceinline__ unsigned pack_f8x4(__half2 lo, __half2 hi) {
    return (unsigned)h2_to_e4m3x2(lo) | ((unsigned)h2_to_e4m3x2(hi) << 16);
}

// ---------------- fused init: zero degrees + acc_init + loss zero ----------------
__global__ void init_kernel(const float4* __restrict__ user_feat,
                            const float4* __restrict__ item_feat,
                            const int* __restrict__ ui,
                            const int* __restrict__ ii,
                            float* __restrict__ loss_out,
                            int has_loss) {
    const int ZBLK = (U_N + 255) / 256;
    if (blockIdx.x < ZBLK) {
        int t = blockIdx.x * 256 + threadIdx.x;
        if (t < U_N) g_deg_u[t] = 0;
        if (t < I_N) g_deg_i[t] = 0;
        if (t == 0 && has_loss) *loss_out = 0.0f;
        return;
    }
    int t = (blockIdx.x - ZBLK) * 256 + threadIdx.x;  // over B*32
    if (t >= B_N * 32) return;
    int b = t >> 5;
    int d = t & 31;
    ((float4*)g_acc_u)[t] = user_feat[(size_t)ui[b] * 32 + d];
    ((float4*)g_acc_i)[t] = item_feat[(size_t)ii[b] * 32 + d];
}

// ---------------- degree (4 edges/thread, int4 index loads) ----------------
__global__ void degree_kernel(const int4* __restrict__ u_idx4,
                              const int4* __restrict__ i_idx4) {
    int t = blockIdx.x * blockDim.x + threadIdx.x;
    if (t >= E_N / 4) return;
    int4 u = u_idx4[t];
    int4 i = i_idx4[t];
    atomicAdd(&g_deg_u[u.x], 1); atomicAdd(&g_deg_u[u.y], 1);
    atomicAdd(&g_deg_u[u.z], 1); atomicAdd(&g_deg_u[u.w], 1);
    atomicAdd(&g_deg_i[i.x], 1); atomicAdd(&g_deg_i[i.y], 1);
    atomicAdd(&g_deg_i[i.z], 1); atomicAdd(&g_deg_i[i.w], 1);
}

// ---------------- scan phase A: per-chunk partial sums ----------------
__global__ void scan_partial_kernel() {
    bool isU = blockIdx.x < NCH_U;
    const int* deg = isU ? g_deg_u : g_deg_i;
    int* part      = isU ? g_chunk_u : g_chunk_i;
    int  c         = isU ? blockIdx.x : blockIdx.x - NCH_U;
    int  n         = isU ? U_N : I_N;

    int base = c * CHUNK + threadIdx.x * 4;
    int s = 0;
    #pragma unroll
    for (int j = 0; j < 4; j++) {
        int idx = base + j;
        if (idx < n) s += deg[idx];
    }
    #pragma unroll
    for (int o = 16; o > 0; o >>= 1) s += __shfl_down_sync(0xFFFFFFFFu, s, o);
    __shared__ int ws[8];
    if ((threadIdx.x & 31) == 0) ws[threadIdx.x >> 5] = s;
    __syncthreads();
    if (threadIdx.x < 8) {
        int v = ws[threadIdx.x];
        #pragma unroll
        for (int o = 4; o > 0; o >>= 1) v += __shfl_down_sync(0xFFu, v, o);
        if (threadIdx.x == 0) part[c] = v;
    }
}

// ---------------- scan phase B: one block scans both partial arrays ----------------
__global__ void scan_chunkoff_kernel() {
    __shared__ int buf[128];
    int t = threadIdx.x;

    int v = (t < NCH_U) ? g_chunk_u[t] : 0;
    buf[t] = v; __syncthreads();
    #pragma unroll
    for (int o = 1; o < 128; o <<= 1) {
        int x = (t >= o) ? buf[t - o] : 0;
        __syncthreads(); buf[t] += x; __syncthreads();
    }
    if (t < NCH_U) g_chunk_u[t] = buf[t] - v;
    __syncthreads();

    int v2 = (t < NCH_I) ? g_chunk_i[t] : 0;
    buf[t] = v2; __syncthreads();
    #pragma unroll
    for (int o = 1; o < 128; o <<= 1) {
        int x = (t >= o) ? buf[t - o] : 0;
        __syncthreads(); buf[t] += x; __syncthreads();
    }
    if (t < NCH_I) g_chunk_i[t] = buf[t] - v2;
    if (t == 0) { g_row_u[U_N] = E_N; g_row_i[I_N] = E_N; }
}

// ---------------- scan phase C: local scan + base; init cursors ----------------
__global__ void scan_final_kernel() {
    bool isU = blockIdx.x < NCH_U;
    const int* deg = isU ? g_deg_u : g_deg_i;
    int* row       = isU ? g_row_u : g_row_i;
    int* cur       = isU ? g_cur_u : g_cur_i;
    int  c         = isU ? blockIdx.x : blockIdx.x - NCH_U;
    int  n         = isU ? U_N : I_N;
    int  cbase     = isU ? g_chunk_u[c] : g_chunk_i[c];

    int base = c * CHUNK + threadIdx.x * 4;
    int d[4], e[4];
    int s = 0;
    #pragma unroll
    for (int j = 0; j < 4; j++) {
        int idx = base + j;
        d[j] = (idx < n) ? deg[idx] : 0;
        e[j] = s;
        s += d[j];
    }
    int lane = threadIdx.x & 31, w = threadIdx.x >> 5;
    int inc = s;
    #pragma unroll
    for (int o = 1; o < 32; o <<= 1) {
        int x = __shfl_up_sync(0xFFFFFFFFu, inc, o);
        if (lane >= o) inc += x;
    }
    __shared__ int ws[8];
    if (lane == 31) ws[w] = inc;
    __syncthreads();
    if (threadIdx.x < 8) {
        int v = ws[threadIdx.x];
        #pragma unroll
        for (int o = 1; o < 8; o <<= 1) {
            int x = __shfl_up_sync(0xFFu, v, o);
            if ((int)threadIdx.x >= o) v += x;
        }
        ws[threadIdx.x] = v;
    }
    __syncthreads();
    int excl = inc - s + (w > 0 ? ws[w - 1] : 0) + cbase;
    #pragma unroll
    for (int j = 0; j < 4; j++) {
        int idx = base + j;
        if (idx < n) { int r = excl + e[j]; row[idx] = r; cur[idx] = r; }
    }
}

// ---------------- fused fill (CSR adjacency, pre-shifted cols) + fp8 convert ----------------
#define FILL_BLOCKS_EXACT ((E_N / 4 + 255) / 256)         // 1954
#define CONV_BLOCKS (((U_N + I_N) * 32 + 255) / 256)      // 18750

__global__ void fillconv_kernel(const int4* __restrict__ u_idx4,
                                const int4* __restrict__ i_idx4,
                                const float4* __restrict__ user_feat,
                                const float4* __restrict__ item_feat) {
    if (blockIdx.x < FILL_BLOCKS_EXACT) {
        int t = blockIdx.x * 256 + threadIdx.x;
        if (t >= E_N / 4) return;
        int4 u4 = u_idx4[t];
        int4 i4 = i_idx4[t];
        #pragma unroll
        for (int j = 0; j < 4; j++) {
            int u = (j == 0) ? u4.x : (j == 1) ? u4.y : (j == 2) ? u4.z : u4.w;
            int i = (j == 0) ? i4.x : (j == 1) ? i4.y : (j == 2) ? i4.z : i4.w;
            float nf = rsqrtf((float)g_deg_u[u] * (float)g_deg_i[i]);
            __half2 h2 = __half2half2(__float2half_rn(nf));
            int nb = *reinterpret_cast<int*>(&h2);
            int pu = atomicAdd(&g_cur_u[u], 1);
            g_adj_u[pu] = make_int2(i << 7, nb);   // byte offset of row
            int pi = atomicAdd(&g_cur_i[i], 1);
            g_adj_i[pi] = make_int2(u << 7, nb);
        }
        return;
    }
    int t = (blockIdx.x - FILL_BLOCKS_EXACT) * 256 + threadIdx.x;
    const int nu = U_N * 32;
    const int ni = I_N * 32;
    float4 v; unsigned* dst; int o;
    if (t < nu)           { v = user_feat[t]; dst = g_f8_u[0]; o = t; }
    else if (t < nu + ni) { o = t - nu; v = item_feat[o]; dst = g_f8_i[0]; }
    else return;
    __half2 lo = __floats2half2_rn(v.x * FP8_SCALE, v.y * FP8_SCALE);
    __half2 hi = __floats2half2_rn(v.z * FP8_SCALE, v.w * FP8_SCALE);
    dst[o] = pack_f8x4(lo, hi);
}

// fma-accumulate one fp8x4 word (already loaded) with weight n
#define ACC_WORD(v, n)                                                          \
    do {                                                                        \
        a01 = __hfma2(e4m3x2_to_h2((unsigned short)((v) & 0xFFFFu)), (n), a01); \
        a23 = __hfma2(e4m3x2_to_h2((unsigned short)((v) >> 16)),     (n), a23); \
    } while (0)

// ---------------- gather: warp per row, lane owns one uint32; fused acc warps ----------------
__global__ void gather_kernel(const unsigned* __restrict__ s8_u,
                              const unsigned* __restrict__ s8_i,
                              unsigned* __restrict__ d8_u,
                              unsigned* __restrict__ d8_i,
                              const int* __restrict__ ui,
                              const int* __restrict__ ii,
                              float acc_coef) {
    int w = (blockIdx.x * blockDim.x + threadIdx.x) >> 5;
    int lane = threadIdx.x & 31;

    if (w >= U_N + I_N) {
        int b = w - (U_N + I_N);
        if (b >= B_N || acc_coef == 0.0f) return;
        float c = acc_coef * FP8_INV;
        int t = b * 32 + lane;
        unsigned q = s8_u[(size_t)ui[b] * 32 + lane];
        float2 p = __half22float2(e4m3x2_to_h2((unsigned short)(q & 0xFFFFu)));
        float2 r = __half22float2(e4m3x2_to_h2((unsigned short)(q >> 16)));
        float4 a = ((float4*)g_acc_u)[t];
        a.x += c * p.x; a.y += c * p.y; a.z += c * r.x; a.w += c * r.y;
        ((float4*)g_acc_u)[t] = a;
        unsigned q2 = s8_i[(size_t)ii[b] * 32 + lane];
        p = __half22float2(e4m3x2_to_h2((unsigned short)(q2 & 0xFFFFu)));
        r = __half22float2(e4m3x2_to_h2((unsigned short)(q2 >> 16)));
        float4 ai = ((float4*)g_acc_i)[t];
        ai.x += c * p.x; ai.y += c * p.y; ai.z += c * r.x; ai.w += c * r.y;
        ((float4*)g_acc_i)[t] = ai;
        return;
    }

    const int* rp; const int2* adj;
    const unsigned* src; const unsigned* self; unsigned* dst; int d;
    if (w < U_N) {
        d = w; rp = g_row_u; adj = g_adj_u;
        src = s8_i; self = s8_u; dst = d8_u;
    } else {
        d = w - U_N; rp = g_row_i; adj = g_adj_i;
        src = s8_u; self = s8_i; dst = d8_i;
    }

    int start = rp[d];
    int end   = rp[d + 1];

    // per-lane base pointer: each neighbor load is base + pre-shifted offset
    const char* lane_base = reinterpret_cast<const char*>(src) + ((unsigned)lane << 2);
    #define LDN(off) (*reinterpret_cast<const unsigned*>(lane_base + (unsigned)(off)))

    unsigned sv = self[(size_t)d * 32 + lane];
    __half2 a01 = e4m3x2_to_h2((unsigned short)(sv & 0xFFFFu));
    __half2 a23 = e4m3x2_to_h2((unsigned short)(sv >> 16));

    int k = start;
    if ((k & 1) && k < end) {   // peel to even k for aligned int4 adjacency loads
        int2 e0 = adj[k];
        unsigned v0 = LDN(e0.x);
        ACC_WORD(v0, *reinterpret_cast<__half2*>(&e0.y));
        k++;
    }
    // 8-edge unrolled main loop: 4x LDG.128 adj + 8x LDG.32 rows in flight
    for (; k + 8 <= end; k += 8) {
        const int4* p4 = reinterpret_cast<const int4*>(adj + k);
        int4 A = p4[0];
        int4 B = p4[1];
        int4 C = p4[2];
        int4 D = p4[3];
        unsigned v0 = LDN(A.x);
        unsigned v1 = LDN(A.z);
        unsigned v2 = LDN(B.x);
        unsigned v3 = LDN(B.z);
        unsigned v4 = LDN(C.x);
        unsigned v5 = LDN(C.z);
        unsigned v6 = LDN(D.x);
        unsigned v7 = LDN(D.z);
        ACC_WORD(v0, *reinterpret_cast<__half2*>(&A.y));
        ACC_WORD(v1, *reinterpret_cast<__half2*>(&A.w));
        ACC_WORD(v2, *reinterpret_cast<__half2*>(&B.y));
        ACC_WORD(v3, *reinterpret_cast<__half2*>(&B.w));
        ACC_WORD(v4, *reinterpret_cast<__half2*>(&C.y));
        ACC_WORD(v5, *reinterpret_cast<__half2*>(&C.w));
        ACC_WORD(v6, *reinterpret_cast<__half2*>(&D.y));
        ACC_WORD(v7, *reinterpret_cast<__half2*>(&D.w));
    }
    if (k + 4 <= end) {
        const int4* p4 = reinterpret_cast<const int4*>(adj + k);
        int4 A = p4[0];
        int4 B = p4[1];
        unsigned v0 = LDN(A.x);
        unsigned v1 = LDN(A.z);
        unsigned v2 = LDN(B.x);
        unsigned v3 = LDN(B.z);
        ACC_WORD(v0, *reinterpret_cast<__half2*>(&A.y));
        ACC_WORD(v1, *reinterpret_cast<__half2*>(&A.w));
        ACC_WORD(v2, *reinterpret_cast<__half2*>(&B.y));
        ACC_WORD(v3, *reinterpret_cast<__half2*>(&B.w));
        k += 4;
    }
    for (; k < end; k++) {
        int2 e0 = adj[k];
        unsigned v0 = LDN(e0.x);
        ACC_WORD(v0, *reinterpret_cast<__half2*>(&e0.y));
    }
    #undef LDN

    dst[(size_t)d * 32 + lane] = pack_f8x4(a01, a23);
}

// ---------------- fused final: last-layer acc + dot + sigmoid + BCE ----------------
__global__ void final_kernel(const unsigned* __restrict__ h3_u,
                             const unsigned* __restrict__ h3_i,
                             const int* __restrict__ ui,
                             const int* __restrict__ ii,
                             const float* __restrict__ labels,
                             float* __restrict__ pred_out,
                             float* __restrict__ loss_out,
                             int has_loss) {
    int b = (blockIdx.x * blockDim.x + threadIdx.x) >> 5;
    int lane = threadIdx.x & 31;
    if (b >= B_N) return;

    const float c = 0.25f * FP8_INV;   // layer-3 coefficient
    int t = b * 32 + lane;

    float4 a = ((const float4*)g_acc_u)[t];
    unsigned q = h3_u[(size_t)ui[b] * 32 + lane];
    float2 p = __half22float2(e4m3x2_to_h2((unsigned short)(q & 0xFFFFu)));
    float2 r = __half22float2(e4m3x2_to_h2((unsigned short)(q >> 16)));
    a.x += c * p.x; a.y += c * p.y; a.z += c * r.x; a.w += c * r.y;

    float4 ai = ((const float4*)g_acc_i)[t];
    unsigned q2 = h3_i[(size_t)ii[b] * 32 + lane];
    p = __half22float2(e4m3x2_to_h2((unsigned short)(q2 & 0xFFFFu)));
    r = __half22float2(e4m3x2_to_h2((unsigned short)(q2 >> 16)));
    ai.x += c * p.x; ai.y += c * p.y; ai.z += c * r.x; ai.w += c * r.y;

    float s = a.x * ai.x + a.y * ai.y + a.z * ai.z + a.w * ai.w;
    #pragma unroll
    for (int o = 16; o > 0; o >>= 1)
        s += __shfl_down_sync(0xFFFFFFFFu, s, o);

    if (lane == 0) {
        float z = 1.0f / (1.0f + expf(-s));
        pred_out[b] = z;
        if (has_loss) {
            float lbl = labels[b];
            float term = fmaxf(z, 0.0f) - z * lbl + log1pf(expf(-fabsf(z)));
            atomicAdd(loss_out, term * (1.0f / (float)B_N));
        }
    }
}

// ---------------- host launch ----------------
extern "C" void kernel_launch(void* const* d_in, const int* in_sizes, int n_in,
                              void* d_out, int out_size) {
    const float* user_feat = (const float*)d_in[0];
    const float* item_feat = (const float*)d_in[1];
    const int*   u_idx     = (const int*)d_in[2];
    const int*   i_idx     = (const int*)d_in[3];
    const int*   ui        = (const int*)d_in[4];
    const int*   ii        = (const int*)d_in[5];
    const float* labels    = (const float*)d_in[6];

    float* out = (float*)d_out;
    int has_loss = (out_size > B_N) ? 1 : 0;
    float* pred_out = out + (out_size - B_N);
    float* loss_out = out;

    unsigned *hu_base, *hi_base;
    cudaGetSymbolAddress((void**)&hu_base, g_f8_u);
    cudaGetSymbolAddress((void**)&hi_base, g_f8_i);
    unsigned* hu[2] = { hu_base, hu_base + (size_t)U_N * 32 };
    unsigned* hi[2] = { hi_base, hi_base + (size_t)I_N * 32 };

    const int T = 256;
    const int ZBLK = (U_N + 255) / 256;
    const int init_blocks = ZBLK + (B_N * 32 + 255) / 256;
    const int deg_blocks = (E_N / 4 + T - 1) / T;
    const int fillconv_blocks = FILL_BLOCKS_EXACT + CONV_BLOCKS;
    const int gather_blocks = ((U_N + I_N + B_N) * 32 + T - 1) / T;

    // 1) fused init (zero degrees, acc layer-0 from exact fp32, zero loss)
    init_kernel<<<init_blocks, T>>>((const float4*)user_feat,
                                    (const float4*)item_feat,
                                    ui, ii, loss_out, has_loss);
    // 2) degrees
    degree_kernel<<<deg_blocks, T>>>((const int4*)u_idx, (const int4*)i_idx);
    // 3) row-pointer scan
    scan_partial_kernel<<<NCH_U + NCH_I, 256>>>();
    scan_chunkoff_kernel<<<1, 128>>>();
    scan_final_kernel<<<NCH_U + NCH_I, 256>>>();
    // 4) fused CSR fill (pre-shifted byte-offset columns) + fp8 convert
    fillconv_kernel<<<fillconv_blocks, T>>>((const int4*)u_idx, (const int4*)i_idx,
                                            (const float4*)user_feat,
                                            (const float4*)item_feat);

    // 5) three propagation layers; each also applies the previous layer's acc
    const float coefs[3] = { 0.5f, 1.0f / 3.0f, 0.25f };
    int cur = 0;
    for (int l = 0; l < 3; l++) {
        int nxt = 1 - cur;
        float prev_coef = (l == 0) ? 0.0f : coefs[l - 1];
        gather_kernel<<<gather_blocks, T>>>(hu[cur], hi[cur],
                                            hu[nxt], hi[nxt],
                                            ui, ii, prev_coef);
        cur = nxt;
    }

    // 6) fused final: layer-3 acc + dot + sigmoid + BCE
    final_kernel<<<(B_N * 32 + T - 1) / T, T>>>(hu[cur], hi[cur],
                                                ui, ii, labels,
                                                pred_out, loss_out, has_loss);
}